// round 2
// baseline (speedup 1.0000x reference)
#include <cuda_runtime.h>

#define HH 8192
#define WW 512
#define NPIX (HH * WW)
#define TG22F 0.4142135623730951f

// Static scratch (allocation-free rule): ~44 MB total
__device__ float         g_mag[NPIX];
__device__ unsigned char g_dir[NPIX];
__device__ unsigned char g_mask[NPIX];   // bit0 = weak, bit1 = strong
__device__ int           g_label[NPIX];
__device__ unsigned char g_flag[NPIX];

// --- image fetch with replicate border (cv2 pads the full 8192x512 strip) ---
__device__ __forceinline__ float img_at(const float* __restrict__ x, int r, int w, int c) {
    r = min(max(r, 0), HH - 1);
    w = min(max(w, 0), WW - 1);
    int b = r >> 9, h = r & 511;
    float v = __ldg(&x[(((size_t)(b * 3 + c) * 512 + h) * 512) + w]);
    // exact XLA op order: floor(((x+1)*0.5)*255), then clip — no FMA contraction
    float t = floorf(__fmul_rn(__fmul_rn(__fadd_rn(v, 1.0f), 0.5f), 255.0f));
    return fminf(fmaxf(t, 0.0f), 255.0f);
}

// K1: Sobel + channel argmax + direction quantization
__global__ void k_grad(const float* __restrict__ x) {
    int i = blockIdx.x * blockDim.x + threadIdx.x;
    if (i >= NPIX) return;
    int w = i & (WW - 1), r = i >> 9;

    float bm = -1.0f, bgx = 0.0f, bgy = 0.0f;
#pragma unroll
    for (int c = 0; c < 3; c++) {
        float a00 = img_at(x, r - 1, w - 1, c), a01 = img_at(x, r - 1, w, c), a02 = img_at(x, r - 1, w + 1, c);
        float a10 = img_at(x, r,     w - 1, c),                               a12 = img_at(x, r,     w + 1, c);
        float a20 = img_at(x, r + 1, w - 1, c), a21 = img_at(x, r + 1, w, c), a22 = img_at(x, r + 1, w + 1, c);
        // integer-valued fp32: exact regardless of order
        float gx = (a02 + 2.0f * a12 + a22) - (a00 + 2.0f * a10 + a20);
        float gy = (a20 + 2.0f * a21 + a22) - (a00 + 2.0f * a01 + a02);
        float m = fabsf(gx) + fabsf(gy);
        if (m > bm) { bm = m; bgx = gx; bgy = gy; }   // strict > == first-max (jnp.argmax)
    }
    float ax = fabsf(bgx), ay = fabsf(bgy);
    unsigned char d;
    if (ay < __fmul_rn(TG22F, ax))              d = 0;  // horizontal gradient
    else if (__fmul_rn(ay, TG22F) > ax)         d = 1;  // vertical gradient
    else d = (__fmul_rn(bgx, bgy) >= 0.0f) ? 2 : 3;     // diagonals
    g_mag[i] = bm;
    g_dir[i] = d;
}

__device__ __forceinline__ float mag_at(int r, int w) {
    // NMS neighbors use ZERO padding (reference _shift pads with 0)
    if ((unsigned)r >= (unsigned)HH || (unsigned)w >= (unsigned)WW) return 0.0f;
    return g_mag[r * WW + w];
}

// K2: non-maximum suppression + thresholds + label/flag init
__global__ void k_nms() {
    int i = blockIdx.x * blockDim.x + threadIdx.x;
    if (i >= NPIX) return;
    int w = i & (WW - 1), r = i >> 9;
    float m = g_mag[i];
    int d = g_dir[i];
    float n1, n2;
    if (d == 0)      { n1 = mag_at(r, w - 1);     n2 = mag_at(r, w + 1); }
    else if (d == 1) { n1 = mag_at(r - 1, w);     n2 = mag_at(r + 1, w); }
    else if (d == 2) { n1 = mag_at(r - 1, w - 1); n2 = mag_at(r + 1, w + 1); }
    else             { n1 = mag_at(r - 1, w + 1); n2 = mag_at(r + 1, w - 1); }
    bool keep = (m > n1) && (m >= n2);
    unsigned char msk = 0;
    if (keep && (m > 100.0f)) msk = 1;
    if (keep && (m > 200.0f)) msk = 3;
    g_mask[i]  = msk;
    g_label[i] = i;
    g_flag[i]  = 0;   // must re-zero every call (graph replays)
}

// Union-find find WITH path halving — used only inside k_merge (ECL-CC pattern;
// races here are benign for the final partition).
__device__ __forceinline__ int uf_find(int x) {
    int p = g_label[x];
    while (p != x) {
        int gp = g_label[p];
        if (gp != p) g_label[x] = gp;
        x = p; p = gp;
    }
    return x;
}

// Read-only find: NO writes to other pixels' slots. Safe to run concurrently
// with owner-thread "set own slot to root" writes (those only shorten walks).
__device__ __forceinline__ int uf_find_ro(int x) {
    int p = g_label[x];
    while (p != x) { x = p; p = g_label[x]; }
    return x;
}

// K3: one-pass CCL merge over weak mask (replaces up-to-512 dilate iterations)
__global__ void k_merge() {
    int i = blockIdx.x * blockDim.x + threadIdx.x;
    if (i >= NPIX) return;
    if (!(g_mask[i] & 1)) return;
    int w = i & (WW - 1), r = i >> 9;
    const int dr[4] = {0, 1, 1, 1};
    const int dw[4] = {1, -1, 0, 1};
#pragma unroll
    for (int k = 0; k < 4; k++) {
        int rr = r + dr[k], ww = w + dw[k];
        if ((unsigned)rr >= (unsigned)HH || (unsigned)ww >= (unsigned)WW) continue;
        int j = rr * WW + ww;
        if (!(g_mask[j] & 1)) continue;
        int a = uf_find(i), b = uf_find(j);
        while (a != b) {
            int hi = a > b ? a : b;
            int lo = a > b ? b : a;
            int old = atomicCAS(&g_label[hi], hi, lo);
            if (old == hi) break;
            a = uf_find(old);
            b = uf_find(lo);
        }
    }
}

// K4: compress own slot to root (read-only walk!) + strong pixels flag their root.
// Roots are stable after k_merge, so uf_find_ro returns the true (min-index) root.
__global__ void k_flag() {
    int i = blockIdx.x * blockDim.x + threadIdx.x;
    if (i >= NPIX) return;
    unsigned char msk = g_mask[i];
    if (!(msk & 1)) return;
    int rt = uf_find_ro(i);
    g_label[i] = rt;           // only write to OWN slot, value is the true root
    if (msk & 2) g_flag[rt] = 1;
}

// K5: final ±1 output, broadcast to 3 channels (NCHW).
// Chase to root defensively (exits after one check since k_flag compressed).
__global__ void k_out(float* __restrict__ out) {
    int i = blockIdx.x * blockDim.x + threadIdx.x;
    if (i >= NPIX) return;
    int w = i & (WW - 1), r = i >> 9;
    bool edge = false;
    if (g_mask[i] & 1) {
        int rt = g_label[i];
        int p = g_label[rt];
        while (p != rt) { rt = p; p = g_label[rt]; }
        edge = (g_flag[rt] != 0);
    }
    float val = edge ? 1.0f : -1.0f;
    int b = r >> 9, h = r & 511;
    size_t base = ((size_t)(b * 3) * 512 + h) * 512 + w;
    out[base]                 = val;
    out[base + 512 * 512]     = val;
    out[base + 2 * 512 * 512] = val;
}

extern "C" void kernel_launch(void* const* d_in, const int* in_sizes, int n_in,
                              void* d_out, int out_size) {
    const float* x = (const float*)d_in[0];
    float* out = (float*)d_out;
    const int threads = 256;
    const int blocks = NPIX / threads;
    k_grad<<<blocks, threads>>>(x);
    k_nms<<<blocks, threads>>>();
    k_merge<<<blocks, threads>>>();
    k_flag<<<blocks, threads>>>();
    k_out<<<blocks, threads>>>(out);
}